// round 6
// baseline (speedup 1.0000x reference)
#include <cuda_runtime.h>
#include <cuda_fp16.h>

// Problem constants (match reference)
#define BB 32
#define LL 4096
#define DD 128
#define NN1 4      // N-1 context slots
#define VV 128

// fp16 lookup table: T[k][tok][v], 4*128*128 halves = 128 KB (L1-resident).
// Bias is pre-folded into the k=0 slice.
__device__ __half g_Th[NN1 * VV * VV];

// ---------------------------------------------------------------------------
// Kernel 1: T[k][tok][v] = sum_d emb[tok][d] * W[v][k*128+d]  (+ b[v] at k=0)
// grid = (8 v-groups, 16 tok-groups, 4 k) = 512 blocks, 128 threads.
// ---------------------------------------------------------------------------
#define VPB 16      // v-rows per block
#define TPB 8       // toks per block
#define WPAD 4      // smem row pad (floats)

__global__ void __launch_bounds__(128)
build_table_kernel(const float* __restrict__ emb,
                   const float* __restrict__ W,
                   const float* __restrict__ bvec) {
    const int v0   = blockIdx.x * VPB;
    const int tok0 = blockIdx.y * TPB;
    const int k    = blockIdx.z;

    __shared__ float sw[VPB][DD + WPAD];
    __shared__ float e[TPB][DD + WPAD];

#pragma unroll
    for (int i = 0; i < 4; i++) {
        int idx = i * 128 + threadIdx.x;           // 0..511
        int vi  = idx >> 5;                        // 32 float4 per row
        int c   = idx & 31;
        const float4* wsrc = reinterpret_cast<const float4*>(
            W + (size_t)(v0 + vi) * (NN1 * DD) + k * DD);
        *reinterpret_cast<float4*>(&sw[vi][c * 4]) = __ldg(&wsrc[c]);
    }
    {
        const float4* esrc = reinterpret_cast<const float4*>(emb + (size_t)tok0 * DD);
#pragma unroll
        for (int i = 0; i < 2; i++) {
            int idx = i * 128 + threadIdx.x;       // 0..255
            float4 ev = __ldg(&esrc[idx]);
            int t = idx >> 5;
            int c = idx & 31;
            *reinterpret_cast<float4*>(&e[t][c * 4]) = ev;
        }
    }
    __syncthreads();

    const int vi = threadIdx.x >> 3;               // 0..15
    const int tp = threadIdx.x & 7;                // 0..7

    float acc = 0.0f;
#pragma unroll
    for (int d = 0; d < DD; d += 4) {
        float4 w  = *reinterpret_cast<const float4*>(&sw[vi][d]);
        float4 ea = *reinterpret_cast<const float4*>(&e[tp][d]);
        acc += w.x * ea.x + w.y * ea.y + w.z * ea.z + w.w * ea.w;
    }
    if (k == 0) acc += __ldg(&bvec[v0 + vi]);

    g_Th[(k * VV + tok0 + tp) * VV + v0 + vi] = __float2half_rn(acc);
}

// ---------------------------------------------------------------------------
// Kernel 2: persistent, software-pipelined gather-sum.
// One warp processes a strided sequence of position-PAIRS. Pipeline:
//   iter it: prefetch tokens(it+2); prefetch table rows(it+1); combine+store(it)
// so every load has a full iteration of independent work covering its latency.
// ---------------------------------------------------------------------------
#define GRID_CTAS 592                       // 4 per SM on 148 SMs
#define WARPS_TOT (GRID_CTAS * 8)           // 4736
#define NPAIRS ((BB * LL) / 2)              // 65536
#define ITERS ((NPAIRS + WARPS_TOT - 1) / WARPS_TOT)   // 14

__device__ __forceinline__ float4 combine4(const uint2& u0, const uint2& u1,
                                           const uint2& u2, const uint2& u3) {
    __half2 lo = __hadd2(__hadd2(*(const __half2*)&u0.x, *(const __half2*)&u1.x),
                         __hadd2(*(const __half2*)&u2.x, *(const __half2*)&u3.x));
    __half2 hi = __hadd2(__hadd2(*(const __half2*)&u0.y, *(const __half2*)&u1.y),
                         __hadd2(*(const __half2*)&u2.y, *(const __half2*)&u3.y));
    float2 flo = __half22float2(lo);
    float2 fhi = __half22float2(hi);
    return make_float4(flo.x, flo.y, fhi.x, fhi.y);
}

__global__ void __launch_bounds__(256)
ngram_sum_kernel(const int* __restrict__ x,
                 const float* __restrict__ bvec,
                 float* __restrict__ out) {
    const int lane  = threadIdx.x & 31;
    const int gwarp = blockIdx.x * 8 + (threadIdx.x >> 5);
    const uint2* T = reinterpret_cast<const uint2*>(g_Th);  // 32 uint2 per row

    int  tok[2][5];
    uint2 tb[2][8];

    // Load 5 context tokens for pair p into buffer s (clamped for tail/edge;
    // garbage values are never consumed in those cases).
#define LOAD_TOK(s, p) do {                                              \
        int pp   = (p) < NPAIRS ? (p) : (NPAIRS - 1);                    \
        int pos0 = pp << 1;                                              \
        int j0   = pos0 & (LL - 1);                                      \
        int base = (pos0 >> 12) * LL + (j0 >= NN1 ? j0 - NN1 : 0);       \
        tok[s][0] = __ldg(x + base + 0);                                 \
        tok[s][1] = __ldg(x + base + 1);                                 \
        tok[s][2] = __ldg(x + base + 2);                                 \
        tok[s][3] = __ldg(x + base + 3);                                 \
        tok[s][4] = __ldg(x + base + 4);                                 \
    } while (0)

    // Load the 8 table rows (4 per position) for the pair whose tokens sit
    // in buffer s.
#define LOAD_TBL(s) do {                                                 \
        tb[s][0] = __ldg(&T[((0 * VV + tok[s][0]) << 5) + lane]);        \
        tb[s][1] = __ldg(&T[((1 * VV + tok[s][1]) << 5) + lane]);        \
        tb[s][2] = __ldg(&T[((2 * VV + tok[s][2]) << 5) + lane]);        \
        tb[s][3] = __ldg(&T[((3 * VV + tok[s][3]) << 5) + lane]);        \
        tb[s][4] = __ldg(&T[((0 * VV + tok[s][1]) << 5) + lane]);        \
        tb[s][5] = __ldg(&T[((1 * VV + tok[s][2]) << 5) + lane]);        \
        tb[s][6] = __ldg(&T[((2 * VV + tok[s][3]) << 5) + lane]);        \
        tb[s][7] = __ldg(&T[((3 * VV + tok[s][4]) << 5) + lane]);        \
    } while (0)

    // Prologue: tokens for pairs 0 and 1, table rows for pair 0.
    LOAD_TOK(0, gwarp);
    LOAD_TOK(1, gwarp + WARPS_TOT);
    LOAD_TBL(0);

#pragma unroll 2
    for (int it = 0; it < ITERS; it++) {
        const int s = it & 1;

        // Stage 1: tokens for pair it+2 (overwrites tok[s], whose pair's
        // table rows are already resident in tb[s]).
        LOAD_TOK(s, gwarp + (it + 2) * WARPS_TOT);

        // Stage 2: table rows for pair it+1 (tokens resident in tok[s^1]).
        LOAD_TBL(s ^ 1);

        // Stage 3: combine + store pair it (table rows resident in tb[s]).
        const int p = gwarp + it * WARPS_TOT;
        if (p < NPAIRS) {
            const int pos0 = p << 1;
            const int j0   = pos0 & (LL - 1);
            float4* o = reinterpret_cast<float4*>(out + (size_t)pos0 * VV);
            if (j0 < NN1) {                     // j0 in {0,2}: bias only
                float4 bb = reinterpret_cast<const float4*>(bvec)[lane];
                o[lane]      = bb;
                o[32 + lane] = bb;
            } else {
                o[lane]      = combine4(tb[s][0], tb[s][1], tb[s][2], tb[s][3]);
                o[32 + lane] = combine4(tb[s][4], tb[s][5], tb[s][6], tb[s][7]);
            }
        }
    }
#undef LOAD_TOK
#undef LOAD_TBL
}

// ---------------------------------------------------------------------------
// Launch. Inputs (metadata order): x(int32 B*L), emb(f32 V*D), W(f32 V*4D),
// b(f32 V). Output: f32 B*L*V.
// ---------------------------------------------------------------------------
extern "C" void kernel_launch(void* const* d_in, const int* in_sizes, int n_in,
                              void* d_out, int out_size) {
    const int*   x    = (const int*)d_in[0];
    const float* emb  = (const float*)d_in[1];
    const float* W    = (const float*)d_in[2];
    const float* bvec = (const float*)d_in[3];
    float* out = (float*)d_out;

    dim3 bgrid(VV / VPB, VV / TPB, NN1);        // (8, 16, 4) = 512 blocks
    build_table_kernel<<<bgrid, 128>>>(emb, W, bvec);

    ngram_sum_kernel<<<GRID_CTAS, 256>>>(x, bvec, out);
}